// round 15
// baseline (speedup 1.0000x reference)
#include <cuda_runtime.h>
#include <cuda_fp16.h>
#include <cstdint>

// ============================================================================
// Fully-fused tensor-core GRU (R14 structure), fp16 arithmetic:
//   x: single fp16, w_ih: single fp16 (gx = x*Wih, 24 MMAs)
//   h: fp16 hi+lo, w_hh: single fp16 (gh = (Hh+Hl)*Wh, 24 MMAs)
// 48 MMAs/warp/step (was 60). h keeps 22-bit feedback via Hl term.
// B=2048, T=256, F=128, H=64. 128 blocks x 256 threads; 16 rows/block.
// ============================================================================

#define Bn 2048
#define Tn 256
#define Fn 128
#define Hn 64
#define ROWS 16
#define NTH 256

// smem offsets (bytes)
#define WIH_H 0                 // 192 x 272 fp16
#define WHH_H 52224             // 192 x 144 fp16
#define XB    79872             // x fp16 single: 2 bufs x 4352
#define XSZ   4352
#define HBB   88576             // h fp16: hi bufs [2] then lo bufs [2], 2304 each
#define HSZ   2304
#define HLO   4608
#define HF    97792             // fp32 h_last: 16 x 68
#define SMEMB 102144

__device__ __forceinline__ uint32_t smem_u32(const void* p) {
    uint32_t a;
    asm("{ .reg .u64 t; cvta.to.shared.u64 t, %1; cvt.u32.u64 %0, t; }"
        : "=r"(a) : "l"(p));
    return a;
}
__device__ __forceinline__ void ldsm4(uint32_t* r, uint32_t addr) {
    asm volatile("ldmatrix.sync.aligned.m8n8.x4.shared.b16 {%0,%1,%2,%3}, [%4];"
        : "=r"(r[0]), "=r"(r[1]), "=r"(r[2]), "=r"(r[3]) : "r"(addr));
}
__device__ __forceinline__ void ldsm2(uint32_t* r, uint32_t addr) {
    asm volatile("ldmatrix.sync.aligned.m8n8.x2.shared.b16 {%0,%1}, [%2];"
        : "=r"(r[0]), "=r"(r[1]) : "r"(addr));
}
__device__ __forceinline__ void mma16816(float* c, const uint32_t* a,
                                         uint32_t b0, uint32_t b1) {
    asm volatile(
        "mma.sync.aligned.m16n8k16.row.col.f32.f16.f16.f32 "
        "{%0,%1,%2,%3}, {%4,%5,%6,%7}, {%8,%9}, {%0,%1,%2,%3};"
        : "+f"(c[0]), "+f"(c[1]), "+f"(c[2]), "+f"(c[3])
        : "r"(a[0]), "r"(a[1]), "r"(a[2]), "r"(a[3]), "r"(b0), "r"(b1));
}
__device__ __forceinline__ uint32_t packh2(float a, float b) {
    __half2 h = __floats2half2_rn(a, b);
    return *(uint32_t*)&h;
}
// fp32x4 -> fp16 (8B)
__device__ __forceinline__ void store_w_hi(char* sm, int off_hi, int boff,
                                           float4 v) {
    *(uint2*)(sm + off_hi + boff) =
        make_uint2(packh2(v.x, v.y), packh2(v.z, v.w));
}
// 8 floats -> 8 fp16 -> one 16B store
__device__ __forceinline__ void store_x16(char* sm, int off, int boff,
                                          float4 a, float4 b) {
    uint4 u;
    u.x = packh2(a.x, a.y);
    u.y = packh2(a.z, a.w);
    u.z = packh2(b.x, b.y);
    u.w = packh2(b.z, b.w);
    *(uint4*)(sm + off + boff) = u;
}
__device__ __forceinline__ float tanh_ap(float v) {
    float r;
    asm("tanh.approx.f32 %0, %1;" : "=f"(r) : "f"(v));
    return r;
}
__device__ __forceinline__ float sig_t(float v) {
    return fmaf(0.5f, tanh_ap(0.5f * v), 0.5f);
}

__global__ void __launch_bounds__(NTH, 1)
gru_fused_tc(const float* __restrict__ x,
             const float* __restrict__ w_ih,
             const float* __restrict__ w_hh,
             const float* __restrict__ b_ih,
             const float* __restrict__ b_hh,
             const float* __restrict__ fc_w,
             const float* __restrict__ fc_b,
             float* __restrict__ out) {
    extern __shared__ char sm[];
    const uint32_t sb = smem_u32(sm);
    const int tid = threadIdx.x;
    const int w   = tid >> 5;
    const int l   = tid & 31;
    const int r0  = blockIdx.x * ROWS;

    // per-lane gate columns & biases
    const int u0 = 8 * w + 2 * (l & 3);
    float brz_r[2], brz_z[2], bn_x[2], bn_h[2];
    #pragma unroll
    for (int j = 0; j < 2; ++j) {
        brz_r[j] = b_ih[u0 + j]      + b_hh[u0 + j];
        brz_z[j] = b_ih[64 + u0 + j] + b_hh[64 + u0 + j];
        bn_x[j]  = b_ih[128 + u0 + j];
        bn_h[j]  = b_hh[128 + u0 + j];
    }

    // weights -> smem (single fp16 each)
    {
        const float4* w4 = (const float4*)w_ih;
        #pragma unroll
        for (int j = 0; j < 24; ++j) {
            int idx = j * 256 + tid;
            int row = idx >> 5, c4 = idx & 31;
            store_w_hi(sm, WIH_H, row * 272 + c4 * 8, w4[idx]);
        }
        const float4* v4 = (const float4*)w_hh;
        #pragma unroll
        for (int j = 0; j < 12; ++j) {
            int idx = j * 256 + tid;
            int row = idx >> 4, c4 = idx & 15;
            store_w_hi(sm, WHH_H, row * 144 + c4 * 8, v4[idx]);
        }
        for (int i = tid; i < (4 * HSZ) / 4; i += NTH)
            *(uint32_t*)(sm + HBB + i * 4) = 0u;
    }
    __syncthreads();

    // resident B fragments (warp w owns n-tiles {w, w+8, w+16})
    const int lq = l & 15;
    uint32_t wihH[3][8][2], whhH[3][4][2];
    #pragma unroll
    for (int g = 0; g < 3; ++g) {
        const uint32_t rbase = (uint32_t)(g * 64 + 8 * w + (lq & 7));
        #pragma unroll
        for (int ks = 0; ks < 8; ++ks) {
            uint32_t off = rbase * 272 + ks * 32 + (lq >> 3) * 16;
            ldsm2(wihH[g][ks], sb + WIH_H + off);
        }
        #pragma unroll
        for (int ks = 0; ks < 4; ++ks) {
            uint32_t off = rbase * 144 + ks * 32 + (lq >> 3) * 16;
            ldsm2(whhH[g][ks], sb + WHH_H + off);
        }
    }

    // A-fragment lane addresses
    const int mrow  = (l & 7) + ((l >> 3) & 1) * 8;
    const int khalf = (l >> 4) & 1;
    const uint32_t aX = (uint32_t)(mrow * 272 + khalf * 16);
    const uint32_t aH = (uint32_t)(mrow * 144 + khalf * 16);

    // x prefetch mapping: 16 rows x 32 f4 per step, 2 f4/thread
    const int pr = tid >> 4;
    const int pc = (tid & 15) * 2;
    const float4* x4 = (const float4*)x;
    const size_t xrow = (size_t)(r0 + pr) * (Tn * Fn / 4);

    // preload x(0)->buf0, x(1)->buf1 (fp16 single)
    {
        float4 v0 = x4[xrow + pc];
        float4 v1 = x4[xrow + pc + 1];
        store_x16(sm, XB, pr * 272 + pc * 8, v0, v1);
        v0 = x4[xrow + 32 + pc];
        v1 = x4[xrow + 32 + pc + 1];
        store_x16(sm, XB + XSZ, pr * 272 + pc * 8, v0, v1);
    }
    __syncthreads();

    const int r_l = l >> 2;
    float hold[4] = {0.f, 0.f, 0.f, 0.f};

    // ---- prologue: gx(0) from buf0, biases folded ----
    float gxR[4], gxZ[4], gxNx[4];
    #pragma unroll
    for (int i = 0; i < 4; ++i) {
        gxR[i] = brz_r[i & 1]; gxZ[i] = brz_z[i & 1]; gxNx[i] = bn_x[i & 1];
    }
    {
        const uint32_t xh = sb + XB + aX;
        #pragma unroll
        for (int ks = 0; ks < 8; ++ks) {
            uint32_t ah[4];
            ldsm4(ah, xh + ks * 32);
            mma16816(gxR,  ah, wihH[0][ks][0], wihH[0][ks][1]);
            mma16816(gxZ,  ah, wihH[1][ks][0], wihH[1][ks][1]);
            mma16816(gxNx, ah, wihH[2][ks][0], wihH[2][ks][1]);
        }
    }

    for (int t = 0; t < Tn; ++t) {
        const int cur = t & 1, nxt = cur ^ 1;

        // prefetch x(t+2) from gmem
        float4 p0, p1;
        const bool pf2 = (t + 2 < Tn);
        if (pf2) {
            p0 = x4[xrow + (size_t)(t + 2) * 32 + pc];
            p1 = x4[xrow + (size_t)(t + 2) * 32 + pc + 1];
        }

        // gh accumulators (bn_h folded into ghN) and gx(t+1) accumulators
        float ghR[4], ghZ[4], ghN[4];
        float gxR2[4], gxZ2[4], gxNx2[4];
        #pragma unroll
        for (int i = 0; i < 4; ++i) {
            ghR[i] = 0.f; ghZ[i] = 0.f; ghN[i] = bn_h[i & 1];
            gxR2[i] = brz_r[i & 1]; gxZ2[i] = brz_z[i & 1]; gxNx2[i] = bn_x[i & 1];
        }

        const uint32_t xh = sb + XB + nxt * XSZ + aX;   // x(t+1)
        const uint32_t hh = sb + HBB + cur * HSZ + aH;  // h(t) hi
        const uint32_t hl = hh + HLO;                   // h(t) lo

        // interleaved: per q, gh kstep q (6 MMAs: (Hh+Hl)*Wh) + gx ksteps
        // 2q,2q+1 (3 each)
        #pragma unroll
        for (int q = 0; q < 4; ++q) {
            uint32_t hah[4], hal[4];
            ldsm4(hah, hh + q * 32);
            ldsm4(hal, hl + q * 32);
            #pragma unroll
            for (int s = 0; s < 2; ++s) {
                const int ks = 2 * q + s;
                uint32_t ah[4];
                ldsm4(ah, xh + ks * 32);
                mma16816(gxR2,  ah, wihH[0][ks][0], wihH[0][ks][1]);
                mma16816(gxZ2,  ah, wihH[1][ks][0], wihH[1][ks][1]);
                mma16816(gxNx2, ah, wihH[2][ks][0], wihH[2][ks][1]);
            }
            mma16816(ghR, hah, whhH[0][q][0], whhH[0][q][1]);
            mma16816(ghZ, hah, whhH[1][q][0], whhH[1][q][1]);
            mma16816(ghN, hah, whhH[2][q][0], whhH[2][q][1]);
            mma16816(ghR, hal, whhH[0][q][0], whhH[0][q][1]);
            mma16816(ghZ, hal, whhH[1][q][0], whhH[1][q][1]);
            mma16816(ghN, hal, whhH[2][q][0], whhH[2][q][1]);
        }

        // gates + h update
        #pragma unroll
        for (int idx = 0; idx < 4; ++idx) {
            float rr = sig_t(ghR[idx] + gxR[idx]);
            float zz = sig_t(ghZ[idx] + gxZ[idx]);
            float nn = tanh_ap(gxNx[idx] + rr * ghN[idx]);
            hold[idx] = (1.0f - zz) * nn + zz * hold[idx];
        }

        // store x(t+2) fp16 into buffer parity cur (x(t) is dead)
        if (pf2)
            store_x16(sm, XB + cur * XSZ, pr * 272 + pc * 8, p0, p1);

        // store h(t+1) fp16 hi/lo into nxt buffer
        #pragma unroll
        for (int i = 0; i < 2; ++i) {
            int row = r_l + 8 * i;
            float a0 = hold[2 * i], a1 = hold[2 * i + 1];
            __half2 hb2 = __floats2half2_rn(a0, a1);
            *(uint32_t*)(sm + HBB + nxt * HSZ + row * 144 + u0 * 2) =
                *(uint32_t*)&hb2;
            float e0 = a0 - __half2float(__low2half(hb2));
            float e1 = a1 - __half2float(__high2half(hb2));
            *(uint32_t*)(sm + HBB + HLO + nxt * HSZ + row * 144 + u0 * 2) =
                packh2(e0, e1);
        }

        // rotate gx pipeline
        #pragma unroll
        for (int i = 0; i < 4; ++i) {
            gxR[i] = gxR2[i]; gxZ[i] = gxZ2[i]; gxNx[i] = gxNx2[i];
        }

        __syncthreads();
    }

    // final FC
    float* hf = (float*)(sm + HF);
    #pragma unroll
    for (int i = 0; i < 2; ++i) {
        int row = r_l + 8 * i;
        hf[row * 68 + u0]     = hold[2 * i];
        hf[row * 68 + u0 + 1] = hold[2 * i + 1];
    }
    __syncthreads();
    if (tid < ROWS) {
        float s = fc_b[0];
        #pragma unroll 8
        for (int j = 0; j < Hn; ++j)
            s += hf[tid * 68 + j] * fc_w[j];
        out[r0 + tid] = s;
    }
}

extern "C" void kernel_launch(void* const* d_in, const int* in_sizes, int n_in,
                              void* d_out, int out_size) {
    const float* x    = (const float*)d_in[0];
    const float* w_ih = (const float*)d_in[1];
    const float* w_hh = (const float*)d_in[2];
    const float* b_ih = (const float*)d_in[3];
    const float* b_hh = (const float*)d_in[4];
    const float* fc_w = (const float*)d_in[5];
    const float* fc_b = (const float*)d_in[6];
    float* out = (float*)d_out;

    cudaFuncSetAttribute(gru_fused_tc,
                         cudaFuncAttributeMaxDynamicSharedMemorySize, SMEMB);
    gru_fused_tc<<<Bn / ROWS, NTH, SMEMB>>>(
        x, w_ih, w_hh, b_ih, b_hh, fc_w, fc_b, out);
}

// round 16
// speedup vs baseline: 1.1224x; 1.1224x over previous
#include <cuda_runtime.h>
#include <cuda_fp16.h>
#include <cstdint>

// ============================================================================
// Fully-fused tensor-core GRU (R14 structure + tail trims):
//   x: single fp16, w_ih: single fp16 (gx = x*Wih, 24 MMAs)
//   h: fp16 hi+lo, w_hh: fp16 hi+lo (gh = 3 terms, 36 MMAs)
//   r,z weight rows pre-scaled by 0.5 -> sigmoid = fma(0.5, tanh, 0.5)
//   gh completes early; last 12 gx MMAs overlap the gate chain.
// B=2048, T=256, F=128, H=64. 128 blocks x 256 threads; 16 rows/block.
// ============================================================================

#define Bn 2048
#define Tn 256
#define Fn 128
#define Hn 64
#define ROWS 16
#define NTH 256

// smem offsets (bytes)
#define WIH_H 0                 // 192 x 272 fp16
#define WHH_H 52224             // 192 x 144 fp16 hi
#define WHH_L 79872             // 192 x 144 fp16 lo
#define XB    107520            // x fp16 single: 2 bufs x 4352
#define XSZ   4352
#define HBB   116224            // h fp16: hi bufs [2] then lo bufs [2], 2304 each
#define HSZ   2304
#define HLO   4608
#define HF    125440            // fp32 h_last: 16 x 68
#define SMEMB 129792

__device__ __forceinline__ uint32_t smem_u32(const void* p) {
    uint32_t a;
    asm("{ .reg .u64 t; cvta.to.shared.u64 t, %1; cvt.u32.u64 %0, t; }"
        : "=r"(a) : "l"(p));
    return a;
}
__device__ __forceinline__ void ldsm4(uint32_t* r, uint32_t addr) {
    asm volatile("ldmatrix.sync.aligned.m8n8.x4.shared.b16 {%0,%1,%2,%3}, [%4];"
        : "=r"(r[0]), "=r"(r[1]), "=r"(r[2]), "=r"(r[3]) : "r"(addr));
}
__device__ __forceinline__ void ldsm2(uint32_t* r, uint32_t addr) {
    asm volatile("ldmatrix.sync.aligned.m8n8.x2.shared.b16 {%0,%1}, [%2];"
        : "=r"(r[0]), "=r"(r[1]) : "r"(addr));
}
__device__ __forceinline__ void mma16816(float* c, const uint32_t* a,
                                         uint32_t b0, uint32_t b1) {
    asm volatile(
        "mma.sync.aligned.m16n8k16.row.col.f32.f16.f16.f32 "
        "{%0,%1,%2,%3}, {%4,%5,%6,%7}, {%8,%9}, {%0,%1,%2,%3};"
        : "+f"(c[0]), "+f"(c[1]), "+f"(c[2]), "+f"(c[3])
        : "r"(a[0]), "r"(a[1]), "r"(a[2]), "r"(a[3]), "r"(b0), "r"(b1));
}
__device__ __forceinline__ uint32_t packh2(float a, float b) {
    __half2 h = __floats2half2_rn(a, b);
    return *(uint32_t*)&h;
}
// fp32x4 * scale -> fp16 (8B)
__device__ __forceinline__ void store_w_hi(char* sm, int off_hi, int boff,
                                           float4 v, float s) {
    *(uint2*)(sm + off_hi + boff) =
        make_uint2(packh2(v.x * s, v.y * s), packh2(v.z * s, v.w * s));
}
// fp32x4 * scale -> fp16 hi + lo (8B each)
__device__ __forceinline__ void split_store_w(char* sm, int off_hi, int off_lo,
                                              int boff, float4 v, float s) {
    float vx = v.x * s, vy = v.y * s, vz = v.z * s, vw = v.w * s;
    __half2 h01 = __floats2half2_rn(vx, vy);
    __half2 h23 = __floats2half2_rn(vz, vw);
    *(uint2*)(sm + off_hi + boff) = make_uint2(*(uint32_t*)&h01, *(uint32_t*)&h23);
    float l0 = vx - __half2float(__low2half(h01));
    float l1 = vy - __half2float(__high2half(h01));
    float l2 = vz - __half2float(__low2half(h23));
    float l3 = vw - __half2float(__high2half(h23));
    *(uint2*)(sm + off_lo + boff) = make_uint2(packh2(l0, l1), packh2(l2, l3));
}
// 8 floats -> 8 fp16 -> one 16B store
__device__ __forceinline__ void store_x16(char* sm, int off, int boff,
                                          float4 a, float4 b) {
    uint4 u;
    u.x = packh2(a.x, a.y);
    u.y = packh2(a.z, a.w);
    u.z = packh2(b.x, b.y);
    u.w = packh2(b.z, b.w);
    *(uint4*)(sm + off + boff) = u;
}
__device__ __forceinline__ float tanh_ap(float v) {
    float r;
    asm("tanh.approx.f32 %0, %1;" : "=f"(r) : "f"(v));
    return r;
}

__global__ void __launch_bounds__(NTH, 1)
gru_fused_tc(const float* __restrict__ x,
             const float* __restrict__ w_ih,
             const float* __restrict__ w_hh,
             const float* __restrict__ b_ih,
             const float* __restrict__ b_hh,
             const float* __restrict__ fc_w,
             const float* __restrict__ fc_b,
             float* __restrict__ out) {
    extern __shared__ char sm[];
    const uint32_t sb = smem_u32(sm);
    const int tid = threadIdx.x;
    const int w   = tid >> 5;
    const int l   = tid & 31;
    const int r0  = blockIdx.x * ROWS;

    // per-lane gate columns & biases (r,z biases pre-scaled by 0.5)
    const int u0 = 8 * w + 2 * (l & 3);
    float brz_r[2], brz_z[2], bn_x[2], bn_h[2];
    #pragma unroll
    for (int j = 0; j < 2; ++j) {
        brz_r[j] = 0.5f * (b_ih[u0 + j]      + b_hh[u0 + j]);
        brz_z[j] = 0.5f * (b_ih[64 + u0 + j] + b_hh[64 + u0 + j]);
        bn_x[j]  = b_ih[128 + u0 + j];
        bn_h[j]  = b_hh[128 + u0 + j];
    }

    // weights -> smem (r,z gate rows [0,128) scaled by 0.5; exact in fp16)
    {
        const float4* w4 = (const float4*)w_ih;
        #pragma unroll
        for (int j = 0; j < 24; ++j) {
            int idx = j * 256 + tid;
            int row = idx >> 5, c4 = idx & 31;
            float s = (row < 128) ? 0.5f : 1.0f;
            store_w_hi(sm, WIH_H, row * 272 + c4 * 8, w4[idx], s);
        }
        const float4* v4 = (const float4*)w_hh;
        #pragma unroll
        for (int j = 0; j < 12; ++j) {
            int idx = j * 256 + tid;
            int row = idx >> 4, c4 = idx & 15;
            float s = (row < 128) ? 0.5f : 1.0f;
            split_store_w(sm, WHH_H, WHH_L, row * 144 + c4 * 8, v4[idx], s);
        }
        for (int i = tid; i < (4 * HSZ) / 4; i += NTH)
            *(uint32_t*)(sm + HBB + i * 4) = 0u;
    }
    __syncthreads();

    // resident B fragments (warp w owns n-tiles {w, w+8, w+16})
    const int lq = l & 15;
    uint32_t wihH[3][8][2], whhH[3][4][2], whhL[3][4][2];
    #pragma unroll
    for (int g = 0; g < 3; ++g) {
        const uint32_t rbase = (uint32_t)(g * 64 + 8 * w + (lq & 7));
        #pragma unroll
        for (int ks = 0; ks < 8; ++ks) {
            uint32_t off = rbase * 272 + ks * 32 + (lq >> 3) * 16;
            ldsm2(wihH[g][ks], sb + WIH_H + off);
        }
        #pragma unroll
        for (int ks = 0; ks < 4; ++ks) {
            uint32_t off = rbase * 144 + ks * 32 + (lq >> 3) * 16;
            ldsm2(whhH[g][ks], sb + WHH_H + off);
            ldsm2(whhL[g][ks], sb + WHH_L + off);
        }
    }

    // A-fragment lane addresses
    const int mrow  = (l & 7) + ((l >> 3) & 1) * 8;
    const int khalf = (l >> 4) & 1;
    const uint32_t aX = (uint32_t)(mrow * 272 + khalf * 16);
    const uint32_t aH = (uint32_t)(mrow * 144 + khalf * 16);

    // x prefetch mapping: 16 rows x 32 f4 per step, 2 f4/thread
    const int pr = tid >> 4;
    const int pc = (tid & 15) * 2;
    const float4* x4 = (const float4*)x;
    const size_t xrow = (size_t)(r0 + pr) * (Tn * Fn / 4);

    // preload x(0)->buf0, x(1)->buf1 (fp16 single)
    {
        float4 v0 = x4[xrow + pc];
        float4 v1 = x4[xrow + pc + 1];
        store_x16(sm, XB, pr * 272 + pc * 8, v0, v1);
        v0 = x4[xrow + 32 + pc];
        v1 = x4[xrow + 32 + pc + 1];
        store_x16(sm, XB + XSZ, pr * 272 + pc * 8, v0, v1);
    }
    __syncthreads();

    const int r_l = l >> 2;
    float hold[4] = {0.f, 0.f, 0.f, 0.f};

    // ---- prologue: gx(0) from buf0, biases folded ----
    float gxR[4], gxZ[4], gxNx[4];
    #pragma unroll
    for (int i = 0; i < 4; ++i) {
        gxR[i] = brz_r[i & 1]; gxZ[i] = brz_z[i & 1]; gxNx[i] = bn_x[i & 1];
    }
    {
        const uint32_t xh = sb + XB + aX;
        #pragma unroll
        for (int ks = 0; ks < 8; ++ks) {
            uint32_t ah[4];
            ldsm4(ah, xh + ks * 32);
            mma16816(gxR,  ah, wihH[0][ks][0], wihH[0][ks][1]);
            mma16816(gxZ,  ah, wihH[1][ks][0], wihH[1][ks][1]);
            mma16816(gxNx, ah, wihH[2][ks][0], wihH[2][ks][1]);
        }
    }

    for (int t = 0; t < Tn; ++t) {
        const int cur = t & 1, nxt = cur ^ 1;

        // prefetch x(t+2) from gmem
        float4 p0, p1;
        const bool pf2 = (t + 2 < Tn);
        if (pf2) {
            p0 = x4[xrow + (size_t)(t + 2) * 32 + pc];
            p1 = x4[xrow + (size_t)(t + 2) * 32 + pc + 1];
        }

        // gh accumulators (bn_h folded into ghN) and gx(t+1) accumulators
        float ghR[4], ghZ[4], ghN[4];
        float gxR2[4], gxZ2[4], gxNx2[4];
        #pragma unroll
        for (int i = 0; i < 4; ++i) {
            ghR[i] = 0.f; ghZ[i] = 0.f; ghN[i] = bn_h[i & 1];
            gxR2[i] = brz_r[i & 1]; gxZ2[i] = brz_z[i & 1]; gxNx2[i] = bn_x[i & 1];
        }

        const uint32_t xh = sb + XB + nxt * XSZ + aX;   // x(t+1)
        const uint32_t hh = sb + HBB + cur * HSZ + aH;  // h(t) hi
        const uint32_t hl = hh + HLO;                   // h(t) lo

        // q-loop: gh kstep q (9 MMAs) + gx kstep q (3 MMAs filler)
        #pragma unroll
        for (int q = 0; q < 4; ++q) {
            uint32_t hah[4], hal[4];
            ldsm4(hah, hh + q * 32);
            ldsm4(hal, hl + q * 32);
            {
                uint32_t ah[4];
                ldsm4(ah, xh + q * 32);
                mma16816(gxR2,  ah, wihH[0][q][0], wihH[0][q][1]);
                mma16816(gxZ2,  ah, wihH[1][q][0], wihH[1][q][1]);
                mma16816(gxNx2, ah, wihH[2][q][0], wihH[2][q][1]);
            }
            mma16816(ghR, hah, whhH[0][q][0], whhH[0][q][1]);
            mma16816(ghZ, hah, whhH[1][q][0], whhH[1][q][1]);
            mma16816(ghN, hah, whhH[2][q][0], whhH[2][q][1]);
            mma16816(ghR, hah, whhL[0][q][0], whhL[0][q][1]);
            mma16816(ghZ, hah, whhL[1][q][0], whhL[1][q][1]);
            mma16816(ghN, hah, whhL[2][q][0], whhL[2][q][1]);
            mma16816(ghR, hal, whhH[0][q][0], whhH[0][q][1]);
            mma16816(ghZ, hal, whhH[1][q][0], whhH[1][q][1]);
            mma16816(ghN, hal, whhH[2][q][0], whhH[2][q][1]);
        }

        // trailing gx ksteps 4..7 (12 independent MMAs) — gh drains behind
        // these, and the gate chain below can interleave with their issue.
        #pragma unroll
        for (int ks = 4; ks < 8; ++ks) {
            uint32_t ah[4];
            ldsm4(ah, xh + ks * 32);
            mma16816(gxR2,  ah, wihH[0][ks][0], wihH[0][ks][1]);
            mma16816(gxZ2,  ah, wihH[1][ks][0], wihH[1][ks][1]);
            mma16816(gxNx2, ah, wihH[2][ks][0], wihH[2][ks][1]);
        }

        // gates + h update (sigmoid pre-scale baked into weights)
        #pragma unroll
        for (int idx = 0; idx < 4; ++idx) {
            float rr = fmaf(0.5f, tanh_ap(ghR[idx] + gxR[idx]), 0.5f);
            float zz = fmaf(0.5f, tanh_ap(ghZ[idx] + gxZ[idx]), 0.5f);
            float nn = tanh_ap(gxNx[idx] + rr * ghN[idx]);
            hold[idx] = fmaf(zz, hold[idx] - nn, nn);
        }

        // store x(t+2) fp16 into buffer parity cur (x(t) is dead)
        if (pf2)
            store_x16(sm, XB + cur * XSZ, pr * 272 + pc * 8, p0, p1);

        // store h(t+1) fp16 hi/lo into nxt buffer
        #pragma unroll
        for (int i = 0; i < 2; ++i) {
            int row = r_l + 8 * i;
            float a0 = hold[2 * i], a1 = hold[2 * i + 1];
            __half2 hb2 = __floats2half2_rn(a0, a1);
            *(uint32_t*)(sm + HBB + nxt * HSZ + row * 144 + u0 * 2) =
                *(uint32_t*)&hb2;
            float e0 = a0 - __half2float(__low2half(hb2));
            float e1 = a1 - __half2float(__high2half(hb2));
            *(uint32_t*)(sm + HBB + HLO + nxt * HSZ + row * 144 + u0 * 2) =
                packh2(e0, e1);
        }

        // rotate gx pipeline
        #pragma unroll
        for (int i = 0; i < 4; ++i) {
            gxR[i] = gxR2[i]; gxZ[i] = gxZ2[i]; gxNx[i] = gxNx2[i];
        }

        __syncthreads();
    }

    // final FC
    float* hf = (float*)(sm + HF);
    #pragma unroll
    for (int i = 0; i < 2; ++i) {
        int row = r_l + 8 * i;
        hf[row * 68 + u0]     = hold[2 * i];
        hf[row * 68 + u0 + 1] = hold[2 * i + 1];
    }
    __syncthreads();
    if (tid < ROWS) {
        float s = fc_b[0];
        #pragma unroll 8
        for (int j = 0; j < Hn; ++j)
            s += hf[tid * 68 + j] * fc_w[j];
        out[r0 + tid] = s;
    }
}

extern "C" void kernel_launch(void* const* d_in, const int* in_sizes, int n_in,
                              void* d_out, int out_size) {
    const float* x    = (const float*)d_in[0];
    const float* w_ih = (const float*)d_in[1];
    const float* w_hh = (const float*)d_in[2];
    const float* b_ih = (const float*)d_in[3];
    const float* b_hh = (const float*)d_in[4];
    const float* fc_w = (const float*)d_in[5];
    const float* fc_b = (const float*)d_in[6];
    float* out = (float*)d_out;

    cudaFuncSetAttribute(gru_fused_tc,
                         cudaFuncAttributeMaxDynamicSharedMemorySize, SMEMB);
    gru_fused_tc<<<Bn / ROWS, NTH, SMEMB>>>(
        x, w_ih, w_hh, b_ih, b_hh, fc_w, fc_b, out);
}